// round 1
// baseline (speedup 1.0000x reference)
#include <cuda_runtime.h>
#include <cstdint>
#include <math.h>

// Problem constants
#define Bq 16
#define Nq 4096
#define Cq 81
#define MAXPC 4096   // max candidates per (b,c) AND per image (each roi emits <=1 candidate total)
#define KK 200       // per-class cap and final output count

// ---------------- device scratch (allocation-free rule: __device__ globals) ----------------
__device__ int   g_cnt[Bq * Cq];                        // per-(b,c) candidate counts
__device__ float g_cscore[(size_t)Bq * Cq * MAXPC];     // per-(b,c) candidate scores
__device__ int   g_cidx[(size_t)Bq * Cq * MAXPC];       // per-(b,c) candidate roi indices
__device__ int   g_kcnt[Bq];                            // per-image kept counts
__device__ float g_kscore[Bq * MAXPC];
__device__ float g_kbox[Bq * MAXPC * 4];
__device__ int   g_ktag[Bq * MAXPC];                    // tag = class*4096 + roi_idx (<2^19)

// ---------------- kernel 0: reset counters (graph-replay determinism) ----------------
__global__ void zero_counts_kernel() {
    int i = blockIdx.x * blockDim.x + threadIdx.x;
    if (i < Bq * Cq) g_cnt[i] = 0;
    if (i < Bq) g_kcnt[i] = 0;
}

// ---------------- kernel 1: per-roi argmax + candidate emission ----------------
// One warp per roi. A score can only exceed 0.5 for the argmax class (softmax sums to 1),
// and background (argmax==0) rois are zeroed by the reference, so each roi emits <=1 candidate.
__global__ void argmax_emit_kernel(const float* __restrict__ probs) {
    int warp = (blockIdx.x * blockDim.x + threadIdx.x) >> 5;
    int lane = threadIdx.x & 31;
    if (warp >= Bq * Nq) return;
    const float* p = probs + (size_t)warp * Cq;
    float v = -1.0f;
    int ix = 0;
    for (int i = lane; i < Cq; i += 32) {
        float pv = p[i];
        if (pv > v) { v = pv; ix = i; }   // strict > keeps lowest index within the lane
    }
    // warp argmax reduction, first-max (lowest index) on ties
    for (int off = 16; off; off >>= 1) {
        float ov = __shfl_down_sync(0xffffffffu, v, off);
        int   oi = __shfl_down_sync(0xffffffffu, ix, off);
        if (ov > v || (ov == v && oi < ix)) { v = ov; ix = oi; }
    }
    if (lane == 0 && ix != 0 && v > 0.5f) {
        int b = warp / Nq, n = warp % Nq;
        int bc = b * Cq + ix;
        int pos = atomicAdd(&g_cnt[bc], 1);
        if (pos < MAXPC) {
            g_cscore[(size_t)bc * MAXPC + pos] = v;
            g_cidx[(size_t)bc * MAXPC + pos]   = n;
        }
    }
}

// ---------------- kernel 2: per-(b,c) sort + cap-200 + greedy NMS ----------------
__global__ void per_class_nms_kernel(const float* __restrict__ roi,
                                     const float* __restrict__ deltas) {
    __shared__ unsigned long long skey[MAXPC];   // 32 KB
    __shared__ float sbox[KK * 4];
    __shared__ int   keep[KK];
    __shared__ int   spos[KK];
    __shared__ int   s_base;

    int bc = blockIdx.x;
    int b = bc / Cq, c = bc % Cq;
    int M = g_cnt[bc];
    if (M > MAXPC) M = MAXPC;
    if (M == 0) return;

    int S = 32;
    while (S < M) S <<= 1;

    // key: score bits (positive floats -> uint order == float order) desc,
    // tie -> lower roi index first (matches lax.top_k stability)
    for (int i = threadIdx.x; i < S; i += blockDim.x) {
        unsigned long long key = 0ull;
        if (i < M) {
            float sc = g_cscore[(size_t)bc * MAXPC + i];
            int   idx = g_cidx[(size_t)bc * MAXPC + i];
            key = ((unsigned long long)__float_as_uint(sc) << 32) |
                  (unsigned)(Nq - 1 - idx);
        }
        skey[i] = key;
    }
    __syncthreads();

    // bitonic sort, descending
    for (int k = 2; k <= S; k <<= 1) {
        for (int j = k >> 1; j > 0; j >>= 1) {
            for (int i = threadIdx.x; i < S; i += blockDim.x) {
                int ixj = i ^ j;
                if (ixj > i) {
                    unsigned long long a = skey[i], bv = skey[ixj];
                    bool descseg = ((i & k) == 0);
                    bool sw = descseg ? (a < bv) : (a > bv);
                    if (sw) { skey[i] = bv; skey[ixj] = a; }
                }
            }
            __syncthreads();
        }
    }

    int M2 = (M < KK) ? M : KK;   // reference per-class top-K cap

    // decode boxes for the capped candidate set
    for (int t = threadIdx.x; t < M2; t += blockDim.x) {
        int idx = Nq - 1 - (int)(skey[t] & 0xFFFFFFFFull);
        const float* r = roi + ((size_t)b * Nq + idx) * 4;
        float y1 = r[0], x1 = r[1], y2 = r[2], x2 = r[3];
        float ah = y2 - y1, aw = x2 - x1;
        float acy = y1 + 0.5f * ah, acx = x1 + 0.5f * aw;
        const float* d = deltas + (((size_t)b * Nq + idx) * Cq + c) * 4;
        float dy = d[0] * 0.1f, dx = d[1] * 0.1f;
        float dh = d[2] * 0.2f, dw = d[3] * 0.2f;
        float bh = expf(dh) * ah, bw = expf(dw) * aw;
        float bcy = dy * ah + acy, bcx = dx * aw + acx;
        float oy1 = bcy - 0.5f * bh, ox1 = bcx - 0.5f * bw;
        sbox[t * 4 + 0] = oy1;
        sbox[t * 4 + 1] = ox1;
        sbox[t * 4 + 2] = oy1 + bh;
        sbox[t * 4 + 3] = ox1 + bw;
        keep[t] = 1;
    }
    __syncthreads();

    // greedy NMS (all candidates have score > 0.5 -> all initially valid)
    for (int i = 0; i < M2 - 1; i++) {
        if (keep[i]) {
            float iy1 = sbox[i * 4 + 0], ix1 = sbox[i * 4 + 1];
            float iy2 = sbox[i * 4 + 2], ix2 = sbox[i * 4 + 3];
            float ia = fmaxf(iy2 - iy1, 0.0f) * fmaxf(ix2 - ix1, 0.0f);
            for (int j = i + 1 + threadIdx.x; j < M2; j += blockDim.x) {
                if (keep[j]) {
                    float jy1 = sbox[j * 4 + 0], jx1 = sbox[j * 4 + 1];
                    float jy2 = sbox[j * 4 + 2], jx2 = sbox[j * 4 + 3];
                    float yy1 = fmaxf(iy1, jy1), xx1 = fmaxf(ix1, jx1);
                    float yy2 = fminf(iy2, jy2), xx2 = fminf(ix2, jx2);
                    float inter = fmaxf(yy2 - yy1, 0.0f) * fmaxf(xx2 - xx1, 0.0f);
                    float ja = fmaxf(jy2 - jy1, 0.0f) * fmaxf(jx2 - jx1, 0.0f);
                    float iou = inter / (ia + ja - inter + 1e-8f);
                    if (iou > 0.5f) keep[j] = 0;
                }
            }
        }
        __syncthreads();
    }

    // compact kept candidates into the per-image list
    if (threadIdx.x == 0) {
        int nk = 0;
        for (int t = 0; t < M2; t++) { spos[t] = nk; nk += keep[t]; }
        s_base = atomicAdd(&g_kcnt[b], nk);
    }
    __syncthreads();
    int base = s_base;
    for (int t = threadIdx.x; t < M2; t += blockDim.x) {
        if (keep[t]) {
            int o = base + spos[t];   // total kept per image <= MAXPC by construction
            unsigned long long key = skey[t];
            int idx = Nq - 1 - (int)(key & 0xFFFFFFFFull);
            g_kscore[b * MAXPC + o] = __uint_as_float((unsigned)(key >> 32));
            g_ktag[b * MAXPC + o]   = c * Nq + idx;
            g_kbox[(b * MAXPC + o) * 4 + 0] = sbox[t * 4 + 0];
            g_kbox[(b * MAXPC + o) * 4 + 1] = sbox[t * 4 + 1];
            g_kbox[(b * MAXPC + o) * 4 + 2] = sbox[t * 4 + 2];
            g_kbox[(b * MAXPC + o) * 4 + 3] = sbox[t * 4 + 3];
        }
    }
}

// ---------------- kernel 3: per-image global top-200 + output ----------------
__global__ void finalize_kernel(float* __restrict__ out) {
    __shared__ unsigned long long skey[MAXPC];   // 32 KB
    int b = blockIdx.x;
    int Mi = g_kcnt[b];
    if (Mi > MAXPC) Mi = MAXPC;

    int S = 0;
    if (Mi > 0) { S = 32; while (S < Mi) S <<= 1; }

    // key: score desc; tie -> (class asc, roi idx asc) via inverted tag (matches the
    // reference's flat c*K+rank ordering); low 12 bits carry the storage slot (payload).
    for (int i = threadIdx.x; i < S; i += blockDim.x) {
        unsigned long long key = 0ull;
        if (i < Mi) {
            float sc = g_kscore[b * MAXPC + i];
            int tag = g_ktag[b * MAXPC + i];            // < 2^19
            key = ((unsigned long long)__float_as_uint(sc) << 32) |
                  ((unsigned long long)((0xFFFFFu - (unsigned)tag) & 0xFFFFFu) << 12) |
                  (unsigned long long)(unsigned)i;
        }
        skey[i] = key;
    }
    __syncthreads();

    for (int k = 2; k <= S; k <<= 1) {
        for (int j = k >> 1; j > 0; j >>= 1) {
            for (int i = threadIdx.x; i < S; i += blockDim.x) {
                int ixj = i ^ j;
                if (ixj > i) {
                    unsigned long long a = skey[i], bv = skey[ixj];
                    bool descseg = ((i & k) == 0);
                    bool sw = descseg ? (a < bv) : (a > bv);
                    if (sw) { skey[i] = bv; skey[ixj] = a; }
                }
            }
            __syncthreads();
        }
    }

    // write top-200 (boxes, labels, scores), zero-padding: covers 100% of d_out
    for (int t = threadIdx.x; t < KK; t += blockDim.x) {
        float bx0 = 0.f, bx1 = 0.f, bx2 = 0.f, bx3 = 0.f, lbl = 0.f, scv = 0.f;
        if (t < Mi) {
            unsigned long long key = skey[t];
            scv = __uint_as_float((unsigned)(key >> 32));   // always > 0.5 here
            int slot = (int)(key & 0xFFFull);
            int tag = 0xFFFFF - (int)((key >> 12) & 0xFFFFFull);
            lbl = (float)(tag >> 12);                       // tag / 4096 = class
            const float* bp = &g_kbox[(b * MAXPC + slot) * 4];
            bx0 = fminf(fmaxf(bp[0], 0.0f), 1.0f);
            bx1 = fminf(fmaxf(bp[1], 0.0f), 1.0f);
            bx2 = fminf(fmaxf(bp[2], 0.0f), 1.0f);
            bx3 = fminf(fmaxf(bp[3], 0.0f), 1.0f);
        }
        float* ob = out + ((size_t)b * KK + t) * 4;
        ob[0] = bx0; ob[1] = bx1; ob[2] = bx2; ob[3] = bx3;
        out[(size_t)Bq * KK * 4 + (size_t)b * KK + t] = lbl;
        out[(size_t)Bq * KK * 4 + (size_t)Bq * KK + (size_t)b * KK + t] = scv;
    }
}

// ---------------- host launch ----------------
extern "C" void kernel_launch(void* const* d_in, const int* in_sizes, int n_in,
                              void* d_out, int out_size) {
    // identify inputs by element count (defensive vs. metadata ordering)
    const float* roi = nullptr;     // B*N*4       = 262144
    const float* deltas = nullptr;  // B*N*C*4     = 21233664
    const float* probs = nullptr;   // B*N*C       = 5308416
    for (int i = 0; i < n_in; i++) {
        if (in_sizes[i] == Bq * Nq * 4)           roi    = (const float*)d_in[i];
        else if (in_sizes[i] == Bq * Nq * Cq * 4) deltas = (const float*)d_in[i];
        else if (in_sizes[i] == Bq * Nq * Cq)     probs  = (const float*)d_in[i];
    }
    float* out = (float*)d_out;

    zero_counts_kernel<<<(Bq * Cq + 255) / 256, 256>>>();
    // one warp per roi: B*N warps = 65536 -> 8192 blocks of 8 warps
    argmax_emit_kernel<<<(Bq * Nq * 32) / 256, 256>>>(probs);
    per_class_nms_kernel<<<Bq * Cq, 256>>>(roi, deltas);
    finalize_kernel<<<Bq, 256>>>(out);
}

// round 2
// speedup vs baseline: 1.6071x; 1.6071x over previous
#include <cuda_runtime.h>
#include <cstdint>
#include <math.h>

// Problem constants
#define Bq 16
#define Nq 4096
#define Cq 81
#define MAXPC 4096   // max candidates per (b,c) AND per image (each roi emits <=1 candidate total)
#define KK 200       // per-class cap and final output count
#define NW 7         // ceil(200/32) words for keep/suppress bitmasks

// ---------------- device scratch (allocation-free rule: __device__ globals) ----------------
__device__ int   g_cnt[Bq * Cq];                        // per-(b,c) candidate counts
__device__ float g_cscore[(size_t)Bq * Cq * MAXPC];     // per-(b,c) candidate scores
__device__ int   g_cidx[(size_t)Bq * Cq * MAXPC];       // per-(b,c) candidate roi indices
__device__ int   g_kcnt[Bq];                            // per-image kept counts
__device__ float g_kscore[Bq * MAXPC];
__device__ float g_kbox[Bq * MAXPC * 4];
__device__ int   g_ktag[Bq * MAXPC];                    // tag = class*4096 + roi_idx (<2^19)

// ---------------- kernel 0: reset counters (graph-replay determinism) ----------------
__global__ void zero_counts_kernel() {
    int i = blockIdx.x * blockDim.x + threadIdx.x;
    if (i < Bq * Cq) g_cnt[i] = 0;
    if (i < Bq) g_kcnt[i] = 0;
}

// ---------------- kernel 1: per-roi argmax + candidate emission ----------------
// One warp per roi. A softmax score can only exceed 0.5 for the argmax class, and
// background (argmax==0) rois are zeroed by the reference, so each roi emits <=1 candidate.
__global__ void argmax_emit_kernel(const float* __restrict__ probs) {
    int warp = (blockIdx.x * blockDim.x + threadIdx.x) >> 5;
    int lane = threadIdx.x & 31;
    if (warp >= Bq * Nq) return;
    const float* p = probs + (size_t)warp * Cq;
    float v = -1.0f;
    int ix = 0;
    for (int i = lane; i < Cq; i += 32) {
        float pv = p[i];
        if (pv > v) { v = pv; ix = i; }   // strict > keeps lowest index within the lane
    }
    for (int off = 16; off; off >>= 1) {
        float ov = __shfl_down_sync(0xffffffffu, v, off);
        int   oi = __shfl_down_sync(0xffffffffu, ix, off);
        if (ov > v || (ov == v && oi < ix)) { v = ov; ix = oi; }
    }
    if (lane == 0 && ix != 0 && v > 0.5f) {
        int b = warp / Nq, n = warp % Nq;
        int bc = b * Cq + ix;
        int pos = atomicAdd(&g_cnt[bc], 1);
        if (pos < MAXPC) {
            g_cscore[(size_t)bc * MAXPC + pos] = v;
            g_cidx[(size_t)bc * MAXPC + pos]   = n;
        }
    }
}

// ---------------- kernel 2: per-(b,c) sort + cap-200 + bitmask greedy NMS ----------------
__global__ void per_class_nms_kernel(const float* __restrict__ roi,
                                     const float* __restrict__ deltas) {
    __shared__ unsigned long long skey[MAXPC];     // 32 KB
    __shared__ float sbox[KK * 4];
    __shared__ unsigned smask[KK * NW];            // suppression bit-matrix: row i = boxes i kills
    __shared__ unsigned skeep[NW];                 // final keep mask
    __shared__ int   s_base;

    int bc = blockIdx.x;
    int b = bc / Cq, c = bc % Cq;
    int M = g_cnt[bc];
    if (M > MAXPC) M = MAXPC;
    if (M == 0) return;

    int S = 32;
    while (S < M) S <<= 1;

    // key: score bits desc, tie -> lower roi index first (matches lax.top_k stability)
    for (int i = threadIdx.x; i < S; i += blockDim.x) {
        unsigned long long key = 0ull;
        if (i < M) {
            float sc = g_cscore[(size_t)bc * MAXPC + i];
            int   idx = g_cidx[(size_t)bc * MAXPC + i];
            key = ((unsigned long long)__float_as_uint(sc) << 32) |
                  (unsigned)(Nq - 1 - idx);
        }
        skey[i] = key;
    }
    __syncthreads();

    for (int k = 2; k <= S; k <<= 1) {
        for (int j = k >> 1; j > 0; j >>= 1) {
            for (int i = threadIdx.x; i < S; i += blockDim.x) {
                int ixj = i ^ j;
                if (ixj > i) {
                    unsigned long long a = skey[i], bv = skey[ixj];
                    bool descseg = ((i & k) == 0);
                    bool sw = descseg ? (a < bv) : (a > bv);
                    if (sw) { skey[i] = bv; skey[ixj] = a; }
                }
            }
            __syncthreads();
        }
    }

    int M2 = (M < KK) ? M : KK;   // reference per-class top-K cap

    // decode boxes for the capped candidate set; zero the bitmask rows
    for (int t = threadIdx.x; t < M2 * NW; t += blockDim.x) smask[t] = 0u;
    for (int t = threadIdx.x; t < M2; t += blockDim.x) {
        int idx = Nq - 1 - (int)(skey[t] & 0xFFFFFFFFull);
        const float* r = roi + ((size_t)b * Nq + idx) * 4;
        float y1 = r[0], x1 = r[1], y2 = r[2], x2 = r[3];
        float ah = y2 - y1, aw = x2 - x1;
        float acy = y1 + 0.5f * ah, acx = x1 + 0.5f * aw;
        const float* d = deltas + (((size_t)b * Nq + idx) * Cq + c) * 4;
        float dy = d[0] * 0.1f, dx = d[1] * 0.1f;
        float dh = d[2] * 0.2f, dw = d[3] * 0.2f;
        float bh = expf(dh) * ah, bw = expf(dw) * aw;
        float bcy = dy * ah + acy, bcx = dx * aw + acx;
        float oy1 = bcy - 0.5f * bh, ox1 = bcx - 0.5f * bw;
        sbox[t * 4 + 0] = oy1;
        sbox[t * 4 + 1] = ox1;
        sbox[t * 4 + 2] = oy1 + bh;
        sbox[t * 4 + 3] = ox1 + bw;
    }
    __syncthreads();

    // parallel IoU bit-matrix over all (i,j>i) pairs — no serial sync loop
    int npairs = M2 * M2;
    for (int t = threadIdx.x; t < npairs; t += blockDim.x) {
        int i = t / M2, j = t % M2;
        if (j > i) {
            float iy1 = sbox[i * 4 + 0], ix1 = sbox[i * 4 + 1];
            float iy2 = sbox[i * 4 + 2], ix2 = sbox[i * 4 + 3];
            float jy1 = sbox[j * 4 + 0], jx1 = sbox[j * 4 + 1];
            float jy2 = sbox[j * 4 + 2], jx2 = sbox[j * 4 + 3];
            float yy1 = fmaxf(iy1, jy1), xx1 = fmaxf(ix1, jx1);
            float yy2 = fminf(iy2, jy2), xx2 = fminf(ix2, jx2);
            float inter = fmaxf(yy2 - yy1, 0.0f) * fmaxf(xx2 - xx1, 0.0f);
            float ia = fmaxf(iy2 - iy1, 0.0f) * fmaxf(ix2 - ix1, 0.0f);
            float ja = fmaxf(jy2 - jy1, 0.0f) * fmaxf(jx2 - jx1, 0.0f);
            float iou = inter / (ia + ja - inter + 1e-8f);
            if (iou > 0.5f)
                atomicOr(&smask[i * NW + (j >> 5)], 1u << (j & 31));
        }
    }
    __syncthreads();

    // greedy scan in ONE warp: keep mask lives in lanes 0..NW-1, decision bit via shfl
    if (threadIdx.x < 32) {
        int w = threadIdx.x;                     // lane == word index (lanes >= NW idle)
        unsigned kw = 0u;
        if (w < NW) {
            int lo = w * 32;
            int nb = M2 - lo;
            kw = (nb >= 32) ? 0xFFFFFFFFu : (nb <= 0 ? 0u : ((1u << nb) - 1u));
        }
        for (int i = 0; i < M2; i++) {
            unsigned ow = __shfl_sync(0xffffffffu, kw, i >> 5);
            if ((ow >> (i & 31)) & 1u) {
                if (w < NW) kw &= ~smask[i * NW + w];   // rows only contain bits j>i
            }
        }
        if (w < NW) skeep[w] = kw;
    }
    __syncthreads();

    // popcount-based compaction into the per-image list
    if (threadIdx.x == 0) {
        int nk = 0;
        for (int w = 0; w < NW; w++) nk += __popc(skeep[w]);
        s_base = atomicAdd(&g_kcnt[b], nk);
    }
    __syncthreads();
    int base = s_base;
    for (int t = threadIdx.x; t < M2; t += blockDim.x) {
        int tw = t >> 5, tb = t & 31;
        if ((skeep[tw] >> tb) & 1u) {
            int pos = 0;
            for (int w = 0; w < tw; w++) pos += __popc(skeep[w]);
            pos += __popc(skeep[tw] & ((tb == 0) ? 0u : ((1u << tb) - 1u)));
            int o = base + pos;
            unsigned long long key = skey[t];
            int idx = Nq - 1 - (int)(key & 0xFFFFFFFFull);
            g_kscore[b * MAXPC + o] = __uint_as_float((unsigned)(key >> 32));
            g_ktag[b * MAXPC + o]   = c * Nq + idx;
            g_kbox[(b * MAXPC + o) * 4 + 0] = sbox[t * 4 + 0];
            g_kbox[(b * MAXPC + o) * 4 + 1] = sbox[t * 4 + 1];
            g_kbox[(b * MAXPC + o) * 4 + 2] = sbox[t * 4 + 2];
            g_kbox[(b * MAXPC + o) * 4 + 3] = sbox[t * 4 + 3];
        }
    }
}

// ---------------- kernel 3: per-image global top-200 + output (1024 threads) ----------------
__global__ void finalize_kernel(float* __restrict__ out) {
    __shared__ unsigned long long skey[MAXPC];   // 32 KB
    int b = blockIdx.x;
    int Mi = g_kcnt[b];
    if (Mi > MAXPC) Mi = MAXPC;

    int S = 0;
    if (Mi > 0) { S = 32; while (S < Mi) S <<= 1; }

    // key: score desc; tie -> (class asc, roi idx asc) via inverted tag; low 12 bits = slot
    for (int i = threadIdx.x; i < S; i += blockDim.x) {
        unsigned long long key = 0ull;
        if (i < Mi) {
            float sc = g_kscore[b * MAXPC + i];
            int tag = g_ktag[b * MAXPC + i];            // < 2^19
            key = ((unsigned long long)__float_as_uint(sc) << 32) |
                  ((unsigned long long)((0xFFFFFu - (unsigned)tag) & 0xFFFFFu) << 12) |
                  (unsigned long long)(unsigned)i;
        }
        skey[i] = key;
    }
    __syncthreads();

    for (int k = 2; k <= S; k <<= 1) {
        for (int j = k >> 1; j > 0; j >>= 1) {
            for (int i = threadIdx.x; i < S; i += blockDim.x) {
                int ixj = i ^ j;
                if (ixj > i) {
                    unsigned long long a = skey[i], bv = skey[ixj];
                    bool descseg = ((i & k) == 0);
                    bool sw = descseg ? (a < bv) : (a > bv);
                    if (sw) { skey[i] = bv; skey[ixj] = a; }
                }
            }
            __syncthreads();
        }
    }

    // write top-200 (boxes, labels, scores), zero-padding: covers 100% of d_out
    for (int t = threadIdx.x; t < KK; t += blockDim.x) {
        float bx0 = 0.f, bx1 = 0.f, bx2 = 0.f, bx3 = 0.f, lbl = 0.f, scv = 0.f;
        if (t < Mi) {
            unsigned long long key = skey[t];
            scv = __uint_as_float((unsigned)(key >> 32));   // always > 0.5 here
            int slot = (int)(key & 0xFFFull);
            int tag = 0xFFFFF - (int)((key >> 12) & 0xFFFFFull);
            lbl = (float)(tag >> 12);                       // tag / 4096 = class
            const float* bp = &g_kbox[(b * MAXPC + slot) * 4];
            bx0 = fminf(fmaxf(bp[0], 0.0f), 1.0f);
            bx1 = fminf(fmaxf(bp[1], 0.0f), 1.0f);
            bx2 = fminf(fmaxf(bp[2], 0.0f), 1.0f);
            bx3 = fminf(fmaxf(bp[3], 0.0f), 1.0f);
        }
        float* ob = out + ((size_t)b * KK + t) * 4;
        ob[0] = bx0; ob[1] = bx1; ob[2] = bx2; ob[3] = bx3;
        out[(size_t)Bq * KK * 4 + (size_t)b * KK + t] = lbl;
        out[(size_t)Bq * KK * 4 + (size_t)Bq * KK + (size_t)b * KK + t] = scv;
    }
}

// ---------------- host launch ----------------
extern "C" void kernel_launch(void* const* d_in, const int* in_sizes, int n_in,
                              void* d_out, int out_size) {
    const float* roi = nullptr;     // B*N*4       = 262144
    const float* deltas = nullptr;  // B*N*C*4     = 21233664
    const float* probs = nullptr;   // B*N*C       = 5308416
    for (int i = 0; i < n_in; i++) {
        if (in_sizes[i] == Bq * Nq * 4)           roi    = (const float*)d_in[i];
        else if (in_sizes[i] == Bq * Nq * Cq * 4) deltas = (const float*)d_in[i];
        else if (in_sizes[i] == Bq * Nq * Cq)     probs  = (const float*)d_in[i];
    }
    float* out = (float*)d_out;

    zero_counts_kernel<<<(Bq * Cq + 255) / 256, 256>>>();
    argmax_emit_kernel<<<(Bq * Nq * 32) / 256, 256>>>(probs);
    per_class_nms_kernel<<<Bq * Cq, 256>>>(roi, deltas);
    finalize_kernel<<<Bq, 1024>>>(out);
}

// round 3
// speedup vs baseline: 2.1429x; 1.3333x over previous
#include <cuda_runtime.h>
#include <cstdint>
#include <math.h>

// Problem constants
#define Bq 16
#define Nq 4096
#define Cq 81
#define MAXPC 4096   // max candidates per (b,c) AND per image (each roi emits <=1 candidate total)
#define KK 200       // per-class cap and final output count
#define NW 7         // ceil(200/32) words for keep/suppress bitmasks

// ---------------- device scratch (allocation-free rule: __device__ globals) ----------------
// All counters start zeroed (static init) and are re-zeroed by their consumer kernel each run,
// so every graph replay sees clean state without a dedicated zeroing launch.
__device__ int   g_cnt[Bq * Cq];                        // per-(b,c) candidate counts
__device__ float g_cscore[(size_t)Bq * Cq * MAXPC];     // per-(b,c) candidate scores
__device__ int   g_cidx[(size_t)Bq * Cq * MAXPC];       // per-(b,c) candidate roi indices
__device__ int   g_kcnt[Bq];                            // per-image kept counts
__device__ float g_kscore[Bq * MAXPC];
__device__ float g_kbox[Bq * MAXPC * 4];
__device__ int   g_ktag[Bq * MAXPC];                    // tag = class*4096 + roi_idx (<2^19)

// ---------------- kernel 1: per-roi argmax + candidate emission ----------------
// One warp per roi. A softmax score can only exceed 0.5 for the argmax class, and
// background (argmax==0) rois are zeroed by the reference, so each roi emits <=1 candidate.
__global__ void argmax_emit_kernel(const float* __restrict__ probs) {
    int warp = (blockIdx.x * blockDim.x + threadIdx.x) >> 5;
    int lane = threadIdx.x & 31;
    if (warp >= Bq * Nq) return;
    const float* p = probs + (size_t)warp * Cq;
    float v = -1.0f;
    int ix = 0;
    for (int i = lane; i < Cq; i += 32) {
        float pv = p[i];
        if (pv > v) { v = pv; ix = i; }   // strict > keeps lowest index within the lane
    }
    for (int off = 16; off; off >>= 1) {
        float ov = __shfl_down_sync(0xffffffffu, v, off);
        int   oi = __shfl_down_sync(0xffffffffu, ix, off);
        if (ov > v || (ov == v && oi < ix)) { v = ov; ix = oi; }
    }
    if (lane == 0 && ix != 0 && v > 0.5f) {
        int b = warp / Nq, n = warp % Nq;
        int bc = b * Cq + ix;
        int pos = atomicAdd(&g_cnt[bc], 1);
        if (pos < MAXPC) {
            g_cscore[(size_t)bc * MAXPC + pos] = v;
            g_cidx[(size_t)bc * MAXPC + pos]   = n;
        }
    }
}

// ---------------- kernel 2: per-(b,c) sort + cap-200 + bitmask greedy NMS ----------------
__global__ void per_class_nms_kernel(const float* __restrict__ roi,
                                     const float* __restrict__ deltas) {
    __shared__ unsigned long long skey[MAXPC];     // 32 KB
    __shared__ float sbox[KK * 4];
    __shared__ unsigned smask[KK * NW];            // suppression bit-matrix: row i = boxes i kills
    __shared__ unsigned skeep[NW];                 // final keep mask
    __shared__ int   s_base;

    int bc = blockIdx.x;
    int b = bc / Cq, c = bc % Cq;
    int M = g_cnt[bc];                             // every thread reads M before it is re-zeroed
    if (M > MAXPC) M = MAXPC;
    if (M == 0) return;                            // counter already 0, nothing to reset

    int S = 32;
    while (S < M) S <<= 1;

    // key: score bits desc, tie -> lower roi index first (matches lax.top_k stability)
    for (int i = threadIdx.x; i < S; i += blockDim.x) {
        unsigned long long key = 0ull;
        if (i < M) {
            float sc = g_cscore[(size_t)bc * MAXPC + i];
            int   idx = g_cidx[(size_t)bc * MAXPC + i];
            key = ((unsigned long long)__float_as_uint(sc) << 32) |
                  (unsigned)(Nq - 1 - idx);
        }
        skey[i] = key;
    }
    __syncthreads();
    if (threadIdx.x == 0) g_cnt[bc] = 0;           // reset for next graph replay (post-barrier)

    for (int k = 2; k <= S; k <<= 1) {
        for (int j = k >> 1; j > 0; j >>= 1) {
            for (int i = threadIdx.x; i < S; i += blockDim.x) {
                int ixj = i ^ j;
                if (ixj > i) {
                    unsigned long long a = skey[i], bv = skey[ixj];
                    bool descseg = ((i & k) == 0);
                    bool sw = descseg ? (a < bv) : (a > bv);
                    if (sw) { skey[i] = bv; skey[ixj] = a; }
                }
            }
            __syncthreads();
        }
    }

    int M2 = (M < KK) ? M : KK;   // reference per-class top-K cap

    // decode boxes for the capped candidate set; zero the bitmask rows
    for (int t = threadIdx.x; t < M2 * NW; t += blockDim.x) smask[t] = 0u;
    for (int t = threadIdx.x; t < M2; t += blockDim.x) {
        int idx = Nq - 1 - (int)(skey[t] & 0xFFFFFFFFull);
        const float* r = roi + ((size_t)b * Nq + idx) * 4;
        float y1 = r[0], x1 = r[1], y2 = r[2], x2 = r[3];
        float ah = y2 - y1, aw = x2 - x1;
        float acy = y1 + 0.5f * ah, acx = x1 + 0.5f * aw;
        const float* d = deltas + (((size_t)b * Nq + idx) * Cq + c) * 4;
        float dy = d[0] * 0.1f, dx = d[1] * 0.1f;
        float dh = d[2] * 0.2f, dw = d[3] * 0.2f;
        float bh = expf(dh) * ah, bw = expf(dw) * aw;
        float bcy = dy * ah + acy, bcx = dx * aw + acx;
        float oy1 = bcy - 0.5f * bh, ox1 = bcx - 0.5f * bw;
        sbox[t * 4 + 0] = oy1;
        sbox[t * 4 + 1] = ox1;
        sbox[t * 4 + 2] = oy1 + bh;
        sbox[t * 4 + 3] = ox1 + bw;
    }
    __syncthreads();

    // parallel IoU bit-matrix over all (i,j>i) pairs — no serial sync loop
    int npairs = M2 * M2;
    for (int t = threadIdx.x; t < npairs; t += blockDim.x) {
        int i = t / M2, j = t % M2;
        if (j > i) {
            float iy1 = sbox[i * 4 + 0], ix1 = sbox[i * 4 + 1];
            float iy2 = sbox[i * 4 + 2], ix2 = sbox[i * 4 + 3];
            float jy1 = sbox[j * 4 + 0], jx1 = sbox[j * 4 + 1];
            float jy2 = sbox[j * 4 + 2], jx2 = sbox[j * 4 + 3];
            float yy1 = fmaxf(iy1, jy1), xx1 = fmaxf(ix1, jx1);
            float yy2 = fminf(iy2, jy2), xx2 = fminf(ix2, jx2);
            float inter = fmaxf(yy2 - yy1, 0.0f) * fmaxf(xx2 - xx1, 0.0f);
            float ia = fmaxf(iy2 - iy1, 0.0f) * fmaxf(ix2 - ix1, 0.0f);
            float ja = fmaxf(jy2 - jy1, 0.0f) * fmaxf(jx2 - jx1, 0.0f);
            float iou = inter / (ia + ja - inter + 1e-8f);
            if (iou > 0.5f)
                atomicOr(&smask[i * NW + (j >> 5)], 1u << (j & 31));
        }
    }
    __syncthreads();

    // greedy scan in ONE warp: keep mask lives in lanes 0..NW-1, decision bit via shfl
    if (threadIdx.x < 32) {
        int w = threadIdx.x;                     // lane == word index (lanes >= NW idle)
        unsigned kw = 0u;
        if (w < NW) {
            int lo = w * 32;
            int nb = M2 - lo;
            kw = (nb >= 32) ? 0xFFFFFFFFu : (nb <= 0 ? 0u : ((1u << nb) - 1u));
        }
        for (int i = 0; i < M2; i++) {
            unsigned ow = __shfl_sync(0xffffffffu, kw, i >> 5);
            if ((ow >> (i & 31)) & 1u) {
                if (w < NW) kw &= ~smask[i * NW + w];   // rows only contain bits j>i
            }
        }
        if (w < NW) skeep[w] = kw;
    }
    __syncthreads();

    // popcount-based compaction into the per-image list
    if (threadIdx.x == 0) {
        int nk = 0;
        for (int w = 0; w < NW; w++) nk += __popc(skeep[w]);
        s_base = atomicAdd(&g_kcnt[b], nk);
    }
    __syncthreads();
    int base = s_base;
    for (int t = threadIdx.x; t < M2; t += blockDim.x) {
        int tw = t >> 5, tb = t & 31;
        if ((skeep[tw] >> tb) & 1u) {
            int pos = 0;
            for (int w = 0; w < tw; w++) pos += __popc(skeep[w]);
            pos += __popc(skeep[tw] & ((tb == 0) ? 0u : ((1u << tb) - 1u)));
            int o = base + pos;
            unsigned long long key = skey[t];
            int idx = Nq - 1 - (int)(key & 0xFFFFFFFFull);
            g_kscore[b * MAXPC + o] = __uint_as_float((unsigned)(key >> 32));
            g_ktag[b * MAXPC + o]   = c * Nq + idx;
            g_kbox[(b * MAXPC + o) * 4 + 0] = sbox[t * 4 + 0];
            g_kbox[(b * MAXPC + o) * 4 + 1] = sbox[t * 4 + 1];
            g_kbox[(b * MAXPC + o) * 4 + 2] = sbox[t * 4 + 2];
            g_kbox[(b * MAXPC + o) * 4 + 3] = sbox[t * 4 + 3];
        }
    }
}

// ---------------- kernel 3: per-image top-200 via radix-bucket select + small sort ----------------
// Scores of survivors are all in (0.5, 1.0) -> fp32 exponent is constant, so mantissa bits
// are monotone in score. 256-bucket histogram finds the 200th-largest's bucket; only keys
// in buckets >= that one are compacted and bitonic-sorted (typically a few hundred, not 4096).
__device__ __forceinline__ int score_bucket(unsigned bits) {
    unsigned d = bits - 0x3F000000u;     // (0, 0x800000] for scores in (0.5, 1.0]
    int bk = (int)(d >> 15);
    return bk > 255 ? 255 : bk;
}

__global__ void finalize_kernel(float* __restrict__ out) {
    __shared__ unsigned long long skey[MAXPC];   // 32 KB (worst case all keys in one bucket)
    __shared__ int hist[256];
    __shared__ int s_cnt, s_bsel;

    int b = blockIdx.x;
    int Mi = g_kcnt[b];
    if (Mi > MAXPC) Mi = MAXPC;

    for (int i = threadIdx.x; i < 256; i += blockDim.x) hist[i] = 0;
    if (threadIdx.x == 0) { s_cnt = 0; g_kcnt[b] = 0; }   // reset for next graph replay
    __syncthreads();

    // pass 1: histogram of score buckets
    for (int i = threadIdx.x; i < Mi; i += blockDim.x) {
        unsigned bits = __float_as_uint(g_kscore[b * MAXPC + i]);
        atomicAdd(&hist[score_bucket(bits)], 1);
    }
    __syncthreads();

    // suffix scan from the top bucket: find bucket of the target-th largest score
    if (threadIdx.x == 0) {
        int target = Mi < KK ? Mi : KK;
        int cum = 0, bsel = 0;
        for (int bk = 255; bk >= 0; bk--) {
            cum += hist[bk];
            if (cum >= target) { bsel = bk; break; }
        }
        s_bsel = bsel;
    }
    __syncthreads();
    int bsel = s_bsel;

    // pass 2: compact candidate keys (score desc; tie -> class asc, roi asc via inverted tag;
    // low 12 bits carry the storage slot as payload)
    for (int i = threadIdx.x; i < Mi; i += blockDim.x) {
        unsigned bits = __float_as_uint(g_kscore[b * MAXPC + i]);
        if (score_bucket(bits) >= bsel) {
            int pos = atomicAdd(&s_cnt, 1);
            int tag = g_ktag[b * MAXPC + i];            // < 2^19
            skey[pos] = ((unsigned long long)bits << 32) |
                        ((unsigned long long)((0xFFFFFu - (unsigned)tag) & 0xFFFFFu) << 12) |
                        (unsigned long long)(unsigned)i;
        }
    }
    __syncthreads();
    int cnt = s_cnt;

    int S = 0;
    if (cnt > 0) { S = 32; while (S < cnt) S <<= 1; }
    for (int i = cnt + threadIdx.x; i < S; i += blockDim.x) skey[i] = 0ull;
    __syncthreads();

    // bitonic sort, descending (small S: usually 256-512)
    for (int k = 2; k <= S; k <<= 1) {
        for (int j = k >> 1; j > 0; j >>= 1) {
            for (int i = threadIdx.x; i < S; i += blockDim.x) {
                int ixj = i ^ j;
                if (ixj > i) {
                    unsigned long long a = skey[i], bv = skey[ixj];
                    bool descseg = ((i & k) == 0);
                    bool sw = descseg ? (a < bv) : (a > bv);
                    if (sw) { skey[i] = bv; skey[ixj] = a; }
                }
            }
            __syncthreads();
        }
    }

    // write top-200 (boxes, labels, scores), zero-padding: covers 100% of d_out
    int vlim = cnt < KK ? cnt : KK;                 // == min(KK, Mi) since cnt >= min(KK, Mi)
    for (int t = threadIdx.x; t < KK; t += blockDim.x) {
        float bx0 = 0.f, bx1 = 0.f, bx2 = 0.f, bx3 = 0.f, lbl = 0.f, scv = 0.f;
        if (t < vlim) {
            unsigned long long key = skey[t];
            scv = __uint_as_float((unsigned)(key >> 32));   // always > 0.5 here
            int slot = (int)(key & 0xFFFull);
            int tag = 0xFFFFF - (int)((key >> 12) & 0xFFFFFull);
            lbl = (float)(tag >> 12);                       // tag / 4096 = class
            const float* bp = &g_kbox[(b * MAXPC + slot) * 4];
            bx0 = fminf(fmaxf(bp[0], 0.0f), 1.0f);
            bx1 = fminf(fmaxf(bp[1], 0.0f), 1.0f);
            bx2 = fminf(fmaxf(bp[2], 0.0f), 1.0f);
            bx3 = fminf(fmaxf(bp[3], 0.0f), 1.0f);
        }
        float* ob = out + ((size_t)b * KK + t) * 4;
        ob[0] = bx0; ob[1] = bx1; ob[2] = bx2; ob[3] = bx3;
        out[(size_t)Bq * KK * 4 + (size_t)b * KK + t] = lbl;
        out[(size_t)Bq * KK * 4 + (size_t)Bq * KK + (size_t)b * KK + t] = scv;
    }
}

// ---------------- host launch ----------------
extern "C" void kernel_launch(void* const* d_in, const int* in_sizes, int n_in,
                              void* d_out, int out_size) {
    const float* roi = nullptr;     // B*N*4       = 262144
    const float* deltas = nullptr;  // B*N*C*4     = 21233664
    const float* probs = nullptr;   // B*N*C       = 5308416
    for (int i = 0; i < n_in; i++) {
        if (in_sizes[i] == Bq * Nq * 4)           roi    = (const float*)d_in[i];
        else if (in_sizes[i] == Bq * Nq * Cq * 4) deltas = (const float*)d_in[i];
        else if (in_sizes[i] == Bq * Nq * Cq)     probs  = (const float*)d_in[i];
    }
    float* out = (float*)d_out;

    argmax_emit_kernel<<<(Bq * Nq * 32) / 256, 256>>>(probs);
    per_class_nms_kernel<<<Bq * Cq, 256>>>(roi, deltas);
    finalize_kernel<<<Bq, 1024>>>(out);
}

// round 4
// speedup vs baseline: 2.5969x; 1.2119x over previous
#include <cuda_runtime.h>
#include <cstdint>
#include <math.h>

// Problem constants
#define Bq 16
#define Nq 4096
#define Cq 81
#define MAXPC 4096   // max candidates per (b,c) AND per image (each roi emits <=1 candidate total)
#define KK 200       // per-class cap and final output count
#define NW 7         // ceil(200/32) words for keep/suppress bitmasks

#define ROWS_PB 128  // rows (rois) per argmax block; 128*324B = 41472B smem, 16B-aligned tiles

// ---------------- device scratch (allocation-free rule: __device__ globals) ----------------
// All counters start zeroed (static init) and are re-zeroed by their consumer kernel each run,
// so every graph replay sees clean state without a dedicated zeroing launch.
__device__ int   g_cnt[Bq * Cq];                        // per-(b,c) candidate counts
__device__ float g_cscore[(size_t)Bq * Cq * MAXPC];     // per-(b,c) candidate scores
__device__ int   g_cidx[(size_t)Bq * Cq * MAXPC];       // per-(b,c) candidate roi indices
__device__ int   g_kcnt[Bq];                            // per-image kept counts
__device__ float g_kscore[Bq * MAXPC];
__device__ float g_kbox[Bq * MAXPC * 4];
__device__ int   g_ktag[Bq * MAXPC];                    // tag = class*4096 + roi_idx (<2^19)

// ---------------- kernel 1: staged per-roi argmax + candidate emission ----------------
// Block stages 128 rows via coalesced float4 loads, then one thread scans one row from smem
// (stride 81 -> bank index lane*17+k mod 32: conflict-free). A softmax score can only exceed
// 0.5 for the argmax class, and background (argmax==0) rois are zeroed by the reference,
// so each roi emits <=1 candidate.
__global__ void __launch_bounds__(ROWS_PB) argmax_emit_kernel(const float* __restrict__ probs) {
    __shared__ float srow[ROWS_PB * Cq];   // 41472 B

    int tid = threadIdx.x;
    size_t base_elem = (size_t)blockIdx.x * ROWS_PB * Cq;

    // coalesced float4 staging: 128*81/4 = 2592 vectors
    const float4* __restrict__ src = (const float4*)(probs + base_elem);
    float4* dst = (float4*)srow;
    #pragma unroll
    for (int i = 0; i < (ROWS_PB * Cq / 4) / ROWS_PB; i++)
        dst[i * ROWS_PB + tid] = src[i * ROWS_PB + tid];
    {   // tail: 2592 = 20*128 + 32
        int i = 20 * ROWS_PB + tid;
        if (i < ROWS_PB * Cq / 4) dst[i] = src[i];
    }
    __syncthreads();

    // per-thread argmax over own row, two independent chains to cut dependent latency
    const float* r = srow + tid * Cq;
    float va = r[0]; int ia = 0;                 // covers k = 0..40
    #pragma unroll
    for (int k = 1; k <= 40; k++) {
        float pv = r[k];
        if (pv > va) { va = pv; ia = k; }        // strict > keeps lowest index
    }
    float vb = r[41]; int ib = 41;               // covers k = 41..80
    #pragma unroll
    for (int k = 42; k < Cq; k++) {
        float pv = r[k];
        if (pv > vb) { vb = pv; ib = k; }
    }
    // merge: all indices in chain a are smaller, so b wins only on strict >
    float v = va; int ix = ia;
    if (vb > va) { v = vb; ix = ib; }

    if (ix != 0 && v > 0.5f) {
        int g = blockIdx.x * ROWS_PB + tid;      // global roi id (blocks never straddle images)
        int b = g >> 12, n = g & (Nq - 1);
        int bc = b * Cq + ix;
        int pos = atomicAdd(&g_cnt[bc], 1);
        if (pos < MAXPC) {
            g_cscore[(size_t)bc * MAXPC + pos] = v;
            g_cidx[(size_t)bc * MAXPC + pos]   = n;
        }
    }
}

// ---------------- kernel 2: per-(b,c) sort + cap-200 + bitmask greedy NMS ----------------
__global__ void per_class_nms_kernel(const float* __restrict__ roi,
                                     const float* __restrict__ deltas) {
    __shared__ unsigned long long skey[MAXPC];     // 32 KB
    __shared__ float sbox[KK * 4];
    __shared__ unsigned smask[KK * NW];            // suppression bit-matrix: row i = boxes i kills
    __shared__ unsigned skeep[NW];                 // final keep mask
    __shared__ int   s_base;

    int bc = blockIdx.x;
    int b = bc / Cq, c = bc % Cq;
    int M = g_cnt[bc];                             // every thread reads M before it is re-zeroed
    if (M > MAXPC) M = MAXPC;
    if (M == 0) return;                            // counter already 0, nothing to reset

    int S = 32;
    while (S < M) S <<= 1;

    // key: score bits desc, tie -> lower roi index first (matches lax.top_k stability)
    for (int i = threadIdx.x; i < S; i += blockDim.x) {
        unsigned long long key = 0ull;
        if (i < M) {
            float sc = g_cscore[(size_t)bc * MAXPC + i];
            int   idx = g_cidx[(size_t)bc * MAXPC + i];
            key = ((unsigned long long)__float_as_uint(sc) << 32) |
                  (unsigned)(Nq - 1 - idx);
        }
        skey[i] = key;
    }
    __syncthreads();
    if (threadIdx.x == 0) g_cnt[bc] = 0;           // reset for next graph replay (post-barrier)

    for (int k = 2; k <= S; k <<= 1) {
        for (int j = k >> 1; j > 0; j >>= 1) {
            for (int i = threadIdx.x; i < S; i += blockDim.x) {
                int ixj = i ^ j;
                if (ixj > i) {
                    unsigned long long a = skey[i], bv = skey[ixj];
                    bool descseg = ((i & k) == 0);
                    bool sw = descseg ? (a < bv) : (a > bv);
                    if (sw) { skey[i] = bv; skey[ixj] = a; }
                }
            }
            __syncthreads();
        }
    }

    int M2 = (M < KK) ? M : KK;   // reference per-class top-K cap

    // decode boxes for the capped candidate set; zero the bitmask rows
    for (int t = threadIdx.x; t < M2 * NW; t += blockDim.x) smask[t] = 0u;
    for (int t = threadIdx.x; t < M2; t += blockDim.x) {
        int idx = Nq - 1 - (int)(skey[t] & 0xFFFFFFFFull);
        const float* r = roi + ((size_t)b * Nq + idx) * 4;
        float y1 = r[0], x1 = r[1], y2 = r[2], x2 = r[3];
        float ah = y2 - y1, aw = x2 - x1;
        float acy = y1 + 0.5f * ah, acx = x1 + 0.5f * aw;
        const float* d = deltas + (((size_t)b * Nq + idx) * Cq + c) * 4;
        float dy = d[0] * 0.1f, dx = d[1] * 0.1f;
        float dh = d[2] * 0.2f, dw = d[3] * 0.2f;
        float bh = expf(dh) * ah, bw = expf(dw) * aw;
        float bcy = dy * ah + acy, bcx = dx * aw + acx;
        float oy1 = bcy - 0.5f * bh, ox1 = bcx - 0.5f * bw;
        sbox[t * 4 + 0] = oy1;
        sbox[t * 4 + 1] = ox1;
        sbox[t * 4 + 2] = oy1 + bh;
        sbox[t * 4 + 3] = ox1 + bw;
    }
    __syncthreads();

    // parallel IoU bit-matrix over all (i,j>i) pairs — no serial sync loop
    int npairs = M2 * M2;
    for (int t = threadIdx.x; t < npairs; t += blockDim.x) {
        int i = t / M2, j = t % M2;
        if (j > i) {
            float iy1 = sbox[i * 4 + 0], ix1 = sbox[i * 4 + 1];
            float iy2 = sbox[i * 4 + 2], ix2 = sbox[i * 4 + 3];
            float jy1 = sbox[j * 4 + 0], jx1 = sbox[j * 4 + 1];
            float jy2 = sbox[j * 4 + 2], jx2 = sbox[j * 4 + 3];
            float yy1 = fmaxf(iy1, jy1), xx1 = fmaxf(ix1, jx1);
            float yy2 = fminf(iy2, jy2), xx2 = fminf(ix2, jx2);
            float inter = fmaxf(yy2 - yy1, 0.0f) * fmaxf(xx2 - xx1, 0.0f);
            float ia = fmaxf(iy2 - iy1, 0.0f) * fmaxf(ix2 - ix1, 0.0f);
            float ja = fmaxf(jy2 - jy1, 0.0f) * fmaxf(jx2 - jx1, 0.0f);
            float iou = inter / (ia + ja - inter + 1e-8f);
            if (iou > 0.5f)
                atomicOr(&smask[i * NW + (j >> 5)], 1u << (j & 31));
        }
    }
    __syncthreads();

    // greedy scan in ONE warp: keep mask lives in lanes 0..NW-1, decision bit via shfl
    if (threadIdx.x < 32) {
        int w = threadIdx.x;                     // lane == word index (lanes >= NW idle)
        unsigned kw = 0u;
        if (w < NW) {
            int lo = w * 32;
            int nb = M2 - lo;
            kw = (nb >= 32) ? 0xFFFFFFFFu : (nb <= 0 ? 0u : ((1u << nb) - 1u));
        }
        for (int i = 0; i < M2; i++) {
            unsigned ow = __shfl_sync(0xffffffffu, kw, i >> 5);
            if ((ow >> (i & 31)) & 1u) {
                if (w < NW) kw &= ~smask[i * NW + w];   // rows only contain bits j>i
            }
        }
        if (w < NW) skeep[w] = kw;
    }
    __syncthreads();

    // popcount-based compaction into the per-image list
    if (threadIdx.x == 0) {
        int nk = 0;
        for (int w = 0; w < NW; w++) nk += __popc(skeep[w]);
        s_base = atomicAdd(&g_kcnt[b], nk);
    }
    __syncthreads();
    int base = s_base;
    for (int t = threadIdx.x; t < M2; t += blockDim.x) {
        int tw = t >> 5, tb = t & 31;
        if ((skeep[tw] >> tb) & 1u) {
            int pos = 0;
            for (int w = 0; w < tw; w++) pos += __popc(skeep[w]);
            pos += __popc(skeep[tw] & ((tb == 0) ? 0u : ((1u << tb) - 1u)));
            int o = base + pos;
            unsigned long long key = skey[t];
            int idx = Nq - 1 - (int)(key & 0xFFFFFFFFull);
            g_kscore[b * MAXPC + o] = __uint_as_float((unsigned)(key >> 32));
            g_ktag[b * MAXPC + o]   = c * Nq + idx;
            g_kbox[(b * MAXPC + o) * 4 + 0] = sbox[t * 4 + 0];
            g_kbox[(b * MAXPC + o) * 4 + 1] = sbox[t * 4 + 1];
            g_kbox[(b * MAXPC + o) * 4 + 2] = sbox[t * 4 + 2];
            g_kbox[(b * MAXPC + o) * 4 + 3] = sbox[t * 4 + 3];
        }
    }
}

// ---------------- kernel 3: per-image top-200 via radix-bucket select + small sort ----------------
// Scores of survivors are all in (0.5, 1.0) -> fp32 exponent is constant, so mantissa bits
// are monotone in score. 256-bucket histogram finds the 200th-largest's bucket; only keys
// in buckets >= that one are compacted and bitonic-sorted (typically a few hundred, not 4096).
__device__ __forceinline__ int score_bucket(unsigned bits) {
    unsigned d = bits - 0x3F000000u;     // (0, 0x800000] for scores in (0.5, 1.0]
    int bk = (int)(d >> 15);
    return bk > 255 ? 255 : bk;
}

__global__ void finalize_kernel(float* __restrict__ out) {
    __shared__ unsigned long long skey[MAXPC];   // 32 KB (worst case all keys in one bucket)
    __shared__ int hist[256];
    __shared__ int s_cnt, s_bsel;

    int b = blockIdx.x;
    int Mi = g_kcnt[b];
    if (Mi > MAXPC) Mi = MAXPC;

    for (int i = threadIdx.x; i < 256; i += blockDim.x) hist[i] = 0;
    if (threadIdx.x == 0) { s_cnt = 0; g_kcnt[b] = 0; }   // reset for next graph replay
    __syncthreads();

    // pass 1: histogram of score buckets
    for (int i = threadIdx.x; i < Mi; i += blockDim.x) {
        unsigned bits = __float_as_uint(g_kscore[b * MAXPC + i]);
        atomicAdd(&hist[score_bucket(bits)], 1);
    }
    __syncthreads();

    // suffix scan from the top bucket: find bucket of the target-th largest score
    if (threadIdx.x == 0) {
        int target = Mi < KK ? Mi : KK;
        int cum = 0, bsel = 0;
        for (int bk = 255; bk >= 0; bk--) {
            cum += hist[bk];
            if (cum >= target) { bsel = bk; break; }
        }
        s_bsel = bsel;
    }
    __syncthreads();
    int bsel = s_bsel;

    // pass 2: compact candidate keys (score desc; tie -> class asc, roi asc via inverted tag;
    // low 12 bits carry the storage slot as payload)
    for (int i = threadIdx.x; i < Mi; i += blockDim.x) {
        unsigned bits = __float_as_uint(g_kscore[b * MAXPC + i]);
        if (score_bucket(bits) >= bsel) {
            int pos = atomicAdd(&s_cnt, 1);
            int tag = g_ktag[b * MAXPC + i];            // < 2^19
            skey[pos] = ((unsigned long long)bits << 32) |
                        ((unsigned long long)((0xFFFFFu - (unsigned)tag) & 0xFFFFFu) << 12) |
                        (unsigned long long)(unsigned)i;
        }
    }
    __syncthreads();
    int cnt = s_cnt;

    int S = 0;
    if (cnt > 0) { S = 32; while (S < cnt) S <<= 1; }
    for (int i = cnt + threadIdx.x; i < S; i += blockDim.x) skey[i] = 0ull;
    __syncthreads();

    // bitonic sort, descending (small S: usually 256-512)
    for (int k = 2; k <= S; k <<= 1) {
        for (int j = k >> 1; j > 0; j >>= 1) {
            for (int i = threadIdx.x; i < S; i += blockDim.x) {
                int ixj = i ^ j;
                if (ixj > i) {
                    unsigned long long a = skey[i], bv = skey[ixj];
                    bool descseg = ((i & k) == 0);
                    bool sw = descseg ? (a < bv) : (a > bv);
                    if (sw) { skey[i] = bv; skey[ixj] = a; }
                }
            }
            __syncthreads();
        }
    }

    // write top-200 (boxes, labels, scores), zero-padding: covers 100% of d_out
    int vlim = cnt < KK ? cnt : KK;                 // == min(KK, Mi) since cnt >= min(KK, Mi)
    for (int t = threadIdx.x; t < KK; t += blockDim.x) {
        float bx0 = 0.f, bx1 = 0.f, bx2 = 0.f, bx3 = 0.f, lbl = 0.f, scv = 0.f;
        if (t < vlim) {
            unsigned long long key = skey[t];
            scv = __uint_as_float((unsigned)(key >> 32));   // always > 0.5 here
            int slot = (int)(key & 0xFFFull);
            int tag = 0xFFFFF - (int)((key >> 12) & 0xFFFFFull);
            lbl = (float)(tag >> 12);                       // tag / 4096 = class
            const float* bp = &g_kbox[(b * MAXPC + slot) * 4];
            bx0 = fminf(fmaxf(bp[0], 0.0f), 1.0f);
            bx1 = fminf(fmaxf(bp[1], 0.0f), 1.0f);
            bx2 = fminf(fmaxf(bp[2], 0.0f), 1.0f);
            bx3 = fminf(fmaxf(bp[3], 0.0f), 1.0f);
        }
        float* ob = out + ((size_t)b * KK + t) * 4;
        ob[0] = bx0; ob[1] = bx1; ob[2] = bx2; ob[3] = bx3;
        out[(size_t)Bq * KK * 4 + (size_t)b * KK + t] = lbl;
        out[(size_t)Bq * KK * 4 + (size_t)Bq * KK + (size_t)b * KK + t] = scv;
    }
}

// ---------------- host launch ----------------
extern "C" void kernel_launch(void* const* d_in, const int* in_sizes, int n_in,
                              void* d_out, int out_size) {
    const float* roi = nullptr;     // B*N*4       = 262144
    const float* deltas = nullptr;  // B*N*C*4     = 21233664
    const float* probs = nullptr;   // B*N*C       = 5308416
    for (int i = 0; i < n_in; i++) {
        if (in_sizes[i] == Bq * Nq * 4)           roi    = (const float*)d_in[i];
        else if (in_sizes[i] == Bq * Nq * Cq * 4) deltas = (const float*)d_in[i];
        else if (in_sizes[i] == Bq * Nq * Cq)     probs  = (const float*)d_in[i];
    }
    float* out = (float*)d_out;

    argmax_emit_kernel<<<(Bq * Nq) / ROWS_PB, ROWS_PB>>>(probs);
    per_class_nms_kernel<<<Bq * Cq, 256>>>(roi, deltas);
    finalize_kernel<<<Bq, 1024>>>(out);
}